// round 3
// baseline (speedup 1.0000x reference)
#include <cuda_runtime.h>
#include <cuda_bf16.h>
#include <cstdint>

// ---------------------------------------------------------------------------
// Problem constants (fixed by setup_inputs)
// ---------------------------------------------------------------------------
#define D          128
#define N0_NODES   1081344
#define N1_NODES   67584
#define N2_NODES   6144
#define N3_NODES   1024
#define F0         15
#define F1         10
#define F2         5

// Scratch (no cudaMalloc allowed)
__device__ float g_h1[N1_NODES * D];
__device__ float g_h2[N2_NODES * D];

// ---------------------------------------------------------------------------
// helpers
// ---------------------------------------------------------------------------
__device__ __forceinline__ uint32_t f2tf32(float f) {
    uint32_t r;
    asm volatile("cvt.rna.tf32.f32 %0, %1;" : "=r"(r) : "f"(f));
    return r;
}
__device__ __forceinline__ void mma_tf32(float c[4], const uint32_t a[4],
                                         const uint32_t b[2]) {
    asm volatile(
        "mma.sync.aligned.m16n8k8.row.col.f32.tf32.tf32.f32 "
        "{%0,%1,%2,%3}, {%4,%5,%6,%7}, {%8,%9}, {%0,%1,%2,%3};"
        : "+f"(c[0]), "+f"(c[1]), "+f"(c[2]), "+f"(c[3])
        : "r"(a[0]), "r"(a[1]), "r"(a[2]), "r"(a[3]), "r"(b[0]), "r"(b[1]));
}
__device__ __forceinline__ void ldsm_x4(uint32_t a[4], uint32_t addr) {
    asm volatile("ldmatrix.sync.aligned.m8n8.x4.shared.b16 {%0,%1,%2,%3}, [%4];"
        : "=r"(a[0]), "=r"(a[1]), "=r"(a[2]), "=r"(a[3]) : "r"(addr));
}
__device__ __forceinline__ void ldsm_x2(uint32_t b[2], uint32_t addr) {
    asm volatile("ldmatrix.sync.aligned.m8n8.x2.shared.b16 {%0,%1}, [%2];"
        : "=r"(b[0]), "=r"(b[1]) : "r"(addr));
}
__device__ __forceinline__ void cp_async16(uint32_t saddr, const void* gptr) {
    asm volatile("cp.async.cg.shared.global [%0], [%1], 16;" ::
                 "r"(saddr), "l"(gptr));
}

// ---------------------------------------------------------------------------
// Fused layer kernel: per block of 128 targets
//   phase G: gather-mean F neighbors from x -> A chunks 0/1 (tf32 in smem)
//            (B = [Wl;Wr] concurrently staged raw fp32 via cp.async)
//   GEMM:    out = [agg | x] (128x256) @ [Wl;Wr]^T (256x128), tf32 mma
//   MODE 0:  ReLU + store     MODE 1: log_softmax + store
// ---------------------------------------------------------------------------
#define AS_STRIDE 68                 // words per A row (64 k + pad)
#define BS_STRIDE 260                // words per B row (256 k + pad)
#define AS_WORDS  (128 * AS_STRIDE)  // one chunk buffer
#define BS_WORDS  (128 * BS_STRIDE)
#define SMEM_BYTES ((BS_WORDS + 2 * AS_WORDS) * 4)

template <int F, int MODE>
__global__ void __launch_bounds__(256, 1) fused_layer_kernel(
    const float* __restrict__ x,    // source features [Ns,128]
    const int*   __restrict__ src,  // [Nt*F]
    const float* __restrict__ Wl,
    const float* __restrict__ Wr,
    float* __restrict__ out)
{
    extern __shared__ uint32_t smem[];
    uint32_t* Bs = smem;                // [128 n][260] raw fp32 bits
    uint32_t* As = smem + BS_WORDS;     // [2][128 m][68] tf32 (agg) / raw (x)

    const int tid  = threadIdx.x;
    const int lane = tid & 31;
    const int wid  = tid >> 5;
    const int wm   = wid & 3;           // 4 warp rows x 32 m
    const int wn   = wid >> 2;          // 2 warp cols x 64 n
    const long blockM = (long)blockIdx.x * 128;

    const uint32_t as_base = (uint32_t)__cvta_generic_to_shared(As);
    const uint32_t bs_base = (uint32_t)__cvta_generic_to_shared(Bs);

    // ---- stage B raw via cp.async (group 1), overlaps with gather ----
#pragma unroll
    for (int i = 0; i < 32; i++) {
        int idx = i * 256 + tid;
        int n   = idx >> 6;
        int seg = idx & 63;             // 16B segment: k = seg*4 (0..255)
        const float* g = (seg < 32) ? (Wl + n * 128 + seg * 4)
                                    : (Wr + n * 128 + (seg - 32) * 4);
        cp_async16(bs_base + (uint32_t)(n * BS_STRIDE * 4 + seg * 16), g);
    }
    asm volatile("cp.async.commit_group;" ::);

    // ---- gather-mean: warp w handles targets w*16 .. w*16+15 ----
    {
        const float4* xv = reinterpret_cast<const float4*>(x);
        const float invf = 1.0f / (float)F;
#pragma unroll 1
        for (int i = 0; i < 16; i++) {
            int tr = wid * 16 + i;
            const int* sp = src + (blockM + tr) * F;
            int rows[F];
#pragma unroll
            for (int j = 0; j < F; j++) rows[j] = __ldg(sp + j);
            float4 s = make_float4(0.f, 0.f, 0.f, 0.f);
#pragma unroll
            for (int j = 0; j < F; j++) {
                float4 v = __ldg(&xv[(long)rows[j] * 32 + lane]);
                s.x += v.x; s.y += v.y; s.z += v.z; s.w += v.w;
            }
            uint4 t;
            t.x = f2tf32(s.x * invf); t.y = f2tf32(s.y * invf);
            t.z = f2tf32(s.z * invf); t.w = f2tf32(s.w * invf);
            // k = lane*4 : lane<16 -> chunk buf0, else buf1
            int buf = lane >> 4;
            int kk  = (lane & 15) * 4;
            *reinterpret_cast<uint4*>(As + buf * AS_WORDS + tr * AS_STRIDE + kk) = t;
        }
    }

    float acc[2][8][4];
#pragma unroll
    for (int mi = 0; mi < 2; mi++)
#pragma unroll
        for (int ni = 0; ni < 8; ni++)
#pragma unroll
            for (int q = 0; q < 4; q++) acc[mi][ni][q] = 0.f;

    // fragment lane addresses (same layout as verified round-2 kernel)
    const uint32_t a_lane = (uint32_t)((wm * 32 + (lane & 15)) * (AS_STRIDE * 4)
                                       + (lane >> 4) * 16);
    const uint32_t b_lane = (uint32_t)((wn * 64 + (lane & 7)) * (BS_STRIDE * 4)
                                       + ((lane >> 3) & 1) * 16);

    // x-chunk loader (raw fp32, cvt post-LDSM)
    auto issue_xchunk = [&](int c) {   // c = 2 or 3 -> buf c&1, koff (c&1)*64
        const int koff = (c & 1) * 64;
        const uint32_t sbase = as_base + (uint32_t)(c & 1) * (AS_WORDS * 4);
#pragma unroll
        for (int i = 0; i < 8; i++) {
            int idx = i * 256 + tid;
            int seg = idx & 15;
            int row = idx >> 4;
            cp_async16(sbase + (uint32_t)(row * (AS_STRIDE * 4) + seg * 16),
                       x + (blockM + row) * 128 + koff + seg * 4);
        }
        asm volatile("cp.async.commit_group;" ::);
    };

    // MMA over one 64-k chunk. CVTA: cvt A frags (raw x chunks), B always cvt.
    auto mma_chunk = [&](int c, bool cvtA) {
        const uint32_t abuf = as_base + (uint32_t)(c & 1) * (AS_WORDS * 4);
#pragma unroll
        for (int kb = 0; kb < 64; kb += 8) {
            const int gk = c * 64 + kb;
            uint32_t bf[8][2];
#pragma unroll
            for (int ni = 0; ni < 8; ni++) {
                ldsm_x2(bf[ni], bs_base + b_lane
                                + (uint32_t)(ni * 8 * BS_STRIDE * 4) + gk * 4);
                asm volatile("cvt.rna.tf32.f32 %0, %0;" : "+r"(bf[ni][0]));
                asm volatile("cvt.rna.tf32.f32 %0, %0;" : "+r"(bf[ni][1]));
            }
            uint32_t af[2][4];
#pragma unroll
            for (int mi = 0; mi < 2; mi++) {
                ldsm_x4(af[mi], abuf + a_lane
                                + (uint32_t)(mi * 16 * AS_STRIDE * 4) + kb * 4);
                if (cvtA) {
#pragma unroll
                    for (int q = 0; q < 4; q++)
                        asm volatile("cvt.rna.tf32.f32 %0, %0;" : "+r"(af[mi][q]));
                }
            }
#pragma unroll
            for (int mi = 0; mi < 2; mi++)
#pragma unroll
                for (int ni = 0; ni < 8; ni++)
                    mma_tf32(acc[mi][ni], af[mi], bf[ni]);
        }
    };

    asm volatile("cp.async.wait_group 0;" ::);   // B resident
    __syncthreads();                             // + gather STS visible

    mma_chunk(0, false);
    __syncthreads();
    issue_xchunk(2);                             // buf0 <- x k[0,64)
    mma_chunk(1, false);
    __syncthreads();
    issue_xchunk(3);                             // buf1 <- x k[64,128)
    asm volatile("cp.async.wait_group 1;" ::);   // chunk 2 done
    __syncthreads();
    mma_chunk(2, true);
    __syncthreads();
    asm volatile("cp.async.wait_group 0;" ::);   // chunk 3 done
    __syncthreads();
    mma_chunk(3, true);

    if (MODE == 0) {
        // ---- ReLU epilogue, float2 stores ----
#pragma unroll
        for (int mi = 0; mi < 2; mi++) {
#pragma unroll
            for (int ni = 0; ni < 8; ni++) {
                long row = blockM + wm * 32 + mi * 16 + (lane >> 2);
                int  col = wn * 64 + ni * 8 + (lane & 3) * 2;
                float2 lo = make_float2(fmaxf(acc[mi][ni][0], 0.f),
                                        fmaxf(acc[mi][ni][1], 0.f));
                float2 hi = make_float2(fmaxf(acc[mi][ni][2], 0.f),
                                        fmaxf(acc[mi][ni][3], 0.f));
                *(float2*)(out + row * 128 + col)       = lo;
                *(float2*)(out + (row + 8) * 128 + col) = hi;
            }
        }
    } else {
        // ---- log_softmax epilogue: acc -> smem, warp-per-row reduce ----
        float* Ls = reinterpret_cast<float*>(Bs);   // [128][132]
        __syncthreads();                            // Bs no longer needed
#pragma unroll
        for (int mi = 0; mi < 2; mi++) {
#pragma unroll
            for (int ni = 0; ni < 8; ni++) {
                int row = wm * 32 + mi * 16 + (lane >> 2);
                int col = wn * 64 + ni * 8 + (lane & 3) * 2;
                *(float2*)(Ls + row * 132 + col) =
                    make_float2(acc[mi][ni][0], acc[mi][ni][1]);
                *(float2*)(Ls + (row + 8) * 132 + col) =
                    make_float2(acc[mi][ni][2], acc[mi][ni][3]);
            }
        }
        __syncthreads();
#pragma unroll 1
        for (int i = 0; i < 16; i++) {
            int r = wid * 16 + i;
            float4 v = *reinterpret_cast<float4*>(Ls + r * 132 + lane * 4);
            float m = fmaxf(fmaxf(v.x, v.y), fmaxf(v.z, v.w));
#pragma unroll
            for (int o = 16; o > 0; o >>= 1)
                m = fmaxf(m, __shfl_xor_sync(0xFFFFFFFF, m, o));
            float s = expf(v.x - m) + expf(v.y - m)
                    + expf(v.z - m) + expf(v.w - m);
#pragma unroll
            for (int o = 16; o > 0; o >>= 1)
                s += __shfl_xor_sync(0xFFFFFFFF, s, o);
            float lse = m + logf(s);
            float4 rr = make_float4(v.x - lse, v.y - lse, v.z - lse, v.w - lse);
            *reinterpret_cast<float4*>(out + (blockM + r) * 128 + lane * 4) = rr;
        }
    }
}

// ---------------------------------------------------------------------------
// Launch
// ---------------------------------------------------------------------------
extern "C" void kernel_launch(void* const* d_in, const int* in_sizes, int n_in,
                              void* d_out, int out_size)
{
    const long X_SZ = (long)N0_NODES * D;
    const int  W_SZ = D * D;

    const float* x = nullptr;
    const float* Wl[3] = {nullptr, nullptr, nullptr};
    const float* Wr[3] = {nullptr, nullptr, nullptr};
    const int*   src[3] = {nullptr, nullptr, nullptr};

    if ((long)in_sizes[0] == X_SZ && in_sizes[1] == W_SZ) {
        x = (const float*)d_in[0];
        for (int i = 0; i < 3; i++) {
            Wl[i]  = (const float*)d_in[1 + 2 * i];
            Wr[i]  = (const float*)d_in[2 + 2 * i];
            src[i] = (const int*)  d_in[7 + 2 * i];
        }
    } else if ((long)in_sizes[0] == X_SZ) {
        x = (const float*)d_in[0];
        for (int i = 0; i < 3; i++) {
            src[i] = (const int*)  d_in[1 + 4 * i];
            Wl[i]  = (const float*)d_in[3 + 4 * i];
            Wr[i]  = (const float*)d_in[4 + 4 * i];
        }
    } else {
        for (int i = 0; i < 3; i++) {
            Wl[i]  = (const float*)d_in[i];
            Wr[i]  = (const float*)d_in[3 + i];
            src[i] = (const int*)  d_in[9 + i];
        }
        x = (const float*)d_in[12];
    }

    float *h1, *h2;
    cudaGetSymbolAddress((void**)&h1, g_h1);
    cudaGetSymbolAddress((void**)&h2, g_h2);

    cudaFuncSetAttribute(fused_layer_kernel<F0, 0>,
        cudaFuncAttributeMaxDynamicSharedMemorySize, SMEM_BYTES);
    cudaFuncSetAttribute(fused_layer_kernel<F1, 0>,
        cudaFuncAttributeMaxDynamicSharedMemorySize, SMEM_BYTES);
    cudaFuncSetAttribute(fused_layer_kernel<F2, 1>,
        cudaFuncAttributeMaxDynamicSharedMemorySize, SMEM_BYTES);

    float* out = (float*)d_out;

    fused_layer_kernel<F0, 0><<<N1_NODES / 128, 256, SMEM_BYTES>>>(
        x, src[0], Wl[0], Wr[0], h1);
    fused_layer_kernel<F1, 0><<<N2_NODES / 128, 256, SMEM_BYTES>>>(
        h1, src[1], Wl[1], Wr[1], h2);
    fused_layer_kernel<F2, 1><<<N3_NODES / 128, 256, SMEM_BYTES>>>(
        h2, src[2], Wl[2], Wr[2], out);
}

// round 4
// speedup vs baseline: 1.2602x; 1.2602x over previous
#include <cuda_runtime.h>
#include <cuda_bf16.h>
#include <cstdint>

// ---------------------------------------------------------------------------
// Problem constants (fixed by setup_inputs)
// ---------------------------------------------------------------------------
#define D          128
#define N0_NODES   1081344
#define N1_NODES   67584
#define N2_NODES   6144
#define N3_NODES   1024
#define F0         15
#define F1         10
#define F2         5

// Scratch (no cudaMalloc allowed)
__device__ float g_agg[N1_NODES * D];
__device__ float g_h1 [N1_NODES * D];
__device__ float g_h2 [N2_NODES * D];

// ---------------------------------------------------------------------------
// Aggregation: warp per target, mean of F gathered 512B rows. (control)
// ---------------------------------------------------------------------------
template <int F>
__global__ void __launch_bounds__(256) agg_kernel(
    const float* __restrict__ x, const int* __restrict__ src,
    float* __restrict__ agg, int nt)
{
    int warp = blockIdx.x * 8 + (threadIdx.x >> 5);
    int lane = threadIdx.x & 31;
    if (warp >= nt) return;

    const float4* xv = reinterpret_cast<const float4*>(x);
    const int* sp = src + warp * F;

    int rows[F];
#pragma unroll
    for (int j = 0; j < F; j++) rows[j] = __ldg(sp + j);

    float4 s = make_float4(0.f, 0.f, 0.f, 0.f);
#pragma unroll
    for (int j = 0; j < F; j++) {
        float4 v = __ldg(&xv[(long)rows[j] * 32 + lane]);
        s.x += v.x; s.y += v.y; s.z += v.z; s.w += v.w;
    }
    const float invf = 1.0f / (float)F;
    s.x *= invf; s.y *= invf; s.z *= invf; s.w *= invf;
    reinterpret_cast<float4*>(agg)[(long)warp * 32 + lane] = s;
}

// ---------------------------------------------------------------------------
// helpers
// ---------------------------------------------------------------------------
__device__ __forceinline__ void mma_tf32(float c[4], const uint32_t a[4],
                                         const uint32_t b[2]) {
    asm volatile(
        "mma.sync.aligned.m16n8k8.row.col.f32.tf32.tf32.f32 "
        "{%0,%1,%2,%3}, {%4,%5,%6,%7}, {%8,%9}, {%0,%1,%2,%3};"
        : "+f"(c[0]), "+f"(c[1]), "+f"(c[2]), "+f"(c[3])
        : "r"(a[0]), "r"(a[1]), "r"(a[2]), "r"(a[3]), "r"(b[0]), "r"(b[1]));
}
__device__ __forceinline__ void ldsm_x4(uint32_t a[4], uint32_t addr) {
    asm volatile("ldmatrix.sync.aligned.m8n8.x4.shared.b16 {%0,%1,%2,%3}, [%4];"
        : "=r"(a[0]), "=r"(a[1]), "=r"(a[2]), "=r"(a[3]) : "r"(addr));
}
__device__ __forceinline__ void ldsm_x2(uint32_t b[2], uint32_t addr) {
    asm volatile("ldmatrix.sync.aligned.m8n8.x2.shared.b16 {%0,%1}, [%2];"
        : "=r"(b[0]), "=r"(b[1]) : "r"(addr));
}
__device__ __forceinline__ void cp_async16(uint32_t saddr, const void* gptr) {
    asm volatile("cp.async.cg.shared.global [%0], [%1], 16;" ::
                 "r"(saddr), "l"(gptr));
}

// ---------------------------------------------------------------------------
// Dual GEMM:  out[M,128] = Agg[M,128] @ Wl^T + X[M,128] @ Wr^T
// A = [Agg | X] (M x 256), B = [Wl ; Wr] (n-major, 256 k).
// Block tile 128x128, 8 warps (4m x 2n). All staging raw fp32 via cp.async;
// tf32 conversion applied post-LDSM. MODE 0: ReLU.  MODE 1: log_softmax.
// ---------------------------------------------------------------------------
#define AS_STRIDE 68                 // words per A row (64 k + pad)
#define BS_STRIDE 260                // words per B row (256 k + pad)
#define AS_WORDS  (128 * AS_STRIDE)
#define BS_WORDS  (128 * BS_STRIDE)
#define SMEM_BYTES ((BS_WORDS + 2 * AS_WORDS) * 4)

template <int MODE>
__global__ void __launch_bounds__(256, 1) gemm_dual_kernel(
    const float* __restrict__ Aagg, const float* __restrict__ X,
    const float* __restrict__ Wl,   const float* __restrict__ Wr,
    float* __restrict__ out)
{
    extern __shared__ uint32_t smem[];
    uint32_t* Bs = smem;                // [128 n][260] raw fp32 bits
    uint32_t* As = smem + BS_WORDS;     // [2][128 m][68] raw fp32 bits

    const int tid  = threadIdx.x;
    const int lane = tid & 31;
    const int wid  = tid >> 5;
    const int wm   = wid & 3;           // 4 warp rows x 32 m
    const int wn   = wid >> 2;          // 2 warp cols x 64 n
    const long blockM = (long)blockIdx.x * 128;

    const uint32_t as_base = (uint32_t)__cvta_generic_to_shared(As);
    const uint32_t bs_base = (uint32_t)__cvta_generic_to_shared(Bs);

    // ---- group 0: B = [Wl ; Wr] raw, one shot, max MLP ----
#pragma unroll
    for (int i = 0; i < 32; i++) {
        int idx = i * 256 + tid;
        int n   = idx >> 6;
        int seg = idx & 63;             // 16B segment: k = seg*4
        const float* g = (seg < 32) ? (Wl + n * 128 + seg * 4)
                                    : (Wr + n * 128 + (seg - 32) * 4);
        cp_async16(bs_base + (uint32_t)(n * BS_STRIDE * 4 + seg * 16), g);
    }
    asm volatile("cp.async.commit_group;" ::);

    // ---- A chunk c: 0/1 from Agg k[0,64)/[64,128); 2/3 from X ----
    auto issue_chunk = [&](int c) {
        const float* src = (c < 2) ? Aagg : X;
        const int koff = (c & 1) * 64;
        const uint32_t sbase = as_base + (uint32_t)(c & 1) * (AS_WORDS * 4);
#pragma unroll
        for (int i = 0; i < 8; i++) {
            int idx = i * 256 + tid;
            int seg = idx & 15;
            int row = idx >> 4;
            cp_async16(sbase + (uint32_t)(row * (AS_STRIDE * 4) + seg * 16),
                       src + (blockM + row) * 128 + koff + seg * 4);
        }
        asm volatile("cp.async.commit_group;" ::);
    };

    issue_chunk(0);
    issue_chunk(1);

    float acc[2][8][4];
#pragma unroll
    for (int mi = 0; mi < 2; mi++)
#pragma unroll
        for (int ni = 0; ni < 8; ni++)
#pragma unroll
            for (int q = 0; q < 4; q++) acc[mi][ni][q] = 0.f;

    const uint32_t a_lane = (uint32_t)((wm * 32 + (lane & 15)) * (AS_STRIDE * 4)
                                       + (lane >> 4) * 16);
    const uint32_t b_lane = (uint32_t)((wn * 64 + (lane & 7)) * (BS_STRIDE * 4)
                                       + ((lane >> 3) & 1) * 16);

#pragma unroll 1
    for (int c = 0; c < 4; c++) {
        if (c < 3) asm volatile("cp.async.wait_group 1;" ::);
        else       asm volatile("cp.async.wait_group 0;" ::);
        __syncthreads();

        const uint32_t abuf = as_base + (uint32_t)(c & 1) * (AS_WORDS * 4);
#pragma unroll
        for (int kb = 0; kb < 64; kb += 8) {
            const int gk = c * 64 + kb;
            uint32_t bf[8][2];
#pragma unroll
            for (int ni = 0; ni < 8; ni++) {
                ldsm_x2(bf[ni], bs_base + b_lane
                                + (uint32_t)(ni * 8 * BS_STRIDE * 4) + gk * 4);
                asm volatile("cvt.rna.tf32.f32 %0, %0;" : "+r"(bf[ni][0]));
                asm volatile("cvt.rna.tf32.f32 %0, %0;" : "+r"(bf[ni][1]));
            }
            uint32_t af[2][4];
#pragma unroll
            for (int mi = 0; mi < 2; mi++) {
                ldsm_x4(af[mi], abuf + a_lane
                                + (uint32_t)(mi * 16 * AS_STRIDE * 4) + kb * 4);
#pragma unroll
                for (int q = 0; q < 4; q++)
                    asm volatile("cvt.rna.tf32.f32 %0, %0;" : "+r"(af[mi][q]));
            }
#pragma unroll
            for (int mi = 0; mi < 2; mi++)
#pragma unroll
                for (int ni = 0; ni < 8; ni++)
                    mma_tf32(acc[mi][ni], af[mi], bf[ni]);
        }
        __syncthreads();
        if (c + 2 < 4) issue_chunk(c + 2);
    }

    if (MODE == 0) {
        // ---- ReLU epilogue, float2 stores ----
#pragma unroll
        for (int mi = 0; mi < 2; mi++) {
#pragma unroll
            for (int ni = 0; ni < 8; ni++) {
                long row = blockM + wm * 32 + mi * 16 + (lane >> 2);
                int  col = wn * 64 + ni * 8 + (lane & 3) * 2;
                float2 lo = make_float2(fmaxf(acc[mi][ni][0], 0.f),
                                        fmaxf(acc[mi][ni][1], 0.f));
                float2 hi = make_float2(fmaxf(acc[mi][ni][2], 0.f),
                                        fmaxf(acc[mi][ni][3], 0.f));
                *(float2*)(out + row * 128 + col)       = lo;
                *(float2*)(out + (row + 8) * 128 + col) = hi;
            }
        }
    } else {
        // ---- log_softmax epilogue: acc -> smem, warp-per-row reduce ----
        float* Ls = reinterpret_cast<float*>(Bs);   // [128][132]
        __syncthreads();
#pragma unroll
        for (int mi = 0; mi < 2; mi++) {
#pragma unroll
            for (int ni = 0; ni < 8; ni++) {
                int row = wm * 32 + mi * 16 + (lane >> 2);
                int col = wn * 64 + ni * 8 + (lane & 3) * 2;
                *(float2*)(Ls + row * 132 + col) =
                    make_float2(acc[mi][ni][0], acc[mi][ni][1]);
                *(float2*)(Ls + (row + 8) * 132 + col) =
                    make_float2(acc[mi][ni][2], acc[mi][ni][3]);
            }
        }
        __syncthreads();
#pragma unroll 1
        for (int i = 0; i < 16; i++) {
            int r = wid * 16 + i;
            float4 v = *reinterpret_cast<float4*>(Ls + r * 132 + lane * 4);
            float m = fmaxf(fmaxf(v.x, v.y), fmaxf(v.z, v.w));
#pragma unroll
            for (int o = 16; o > 0; o >>= 1)
                m = fmaxf(m, __shfl_xor_sync(0xFFFFFFFF, m, o));
            float s = expf(v.x - m) + expf(v.y - m)
                    + expf(v.z - m) + expf(v.w - m);
#pragma unroll
            for (int o = 16; o > 0; o >>= 1)
                s += __shfl_xor_sync(0xFFFFFFFF, s, o);
            float lse = m + logf(s);
            float4 rr = make_float4(v.x - lse, v.y - lse, v.z - lse, v.w - lse);
            *reinterpret_cast<float4*>(out + (blockM + r) * 128 + lane * 4) = rr;
        }
    }
}

// ---------------------------------------------------------------------------
// Launch
// ---------------------------------------------------------------------------
extern "C" void kernel_launch(void* const* d_in, const int* in_sizes, int n_in,
                              void* d_out, int out_size)
{
    const long X_SZ = (long)N0_NODES * D;
    const int  W_SZ = D * D;

    const float* x = nullptr;
    const float* Wl[3] = {nullptr, nullptr, nullptr};
    const float* Wr[3] = {nullptr, nullptr, nullptr};
    const int*   src[3] = {nullptr, nullptr, nullptr};

    if ((long)in_sizes[0] == X_SZ && in_sizes[1] == W_SZ) {
        x = (const float*)d_in[0];
        for (int i = 0; i < 3; i++) {
            Wl[i]  = (const float*)d_in[1 + 2 * i];
            Wr[i]  = (const float*)d_in[2 + 2 * i];
            src[i] = (const int*)  d_in[7 + 2 * i];
        }
    } else if ((long)in_sizes[0] == X_SZ) {
        x = (const float*)d_in[0];
        for (int i = 0; i < 3; i++) {
            src[i] = (const int*)  d_in[1 + 4 * i];
            Wl[i]  = (const float*)d_in[3 + 4 * i];
            Wr[i]  = (const float*)d_in[4 + 4 * i];
        }
    } else {
        for (int i = 0; i < 3; i++) {
            Wl[i]  = (const float*)d_in[i];
            Wr[i]  = (const float*)d_in[3 + i];
            src[i] = (const int*)  d_in[9 + i];
        }
        x = (const float*)d_in[12];
    }

    float *agg, *h1, *h2;
    cudaGetSymbolAddress((void**)&agg, g_agg);
    cudaGetSymbolAddress((void**)&h1,  g_h1);
    cudaGetSymbolAddress((void**)&h2,  g_h2);

    cudaFuncSetAttribute(gemm_dual_kernel<0>,
        cudaFuncAttributeMaxDynamicSharedMemorySize, SMEM_BYTES);
    cudaFuncSetAttribute(gemm_dual_kernel<1>,
        cudaFuncAttributeMaxDynamicSharedMemorySize, SMEM_BYTES);

    float* out = (float*)d_out;

    // Layer 0
    agg_kernel<F0><<<N1_NODES / 8, 256>>>(x, src[0], agg, N1_NODES);
    gemm_dual_kernel<0><<<N1_NODES / 128, 256, SMEM_BYTES>>>(
        agg, x, Wl[0], Wr[0], h1);

    // Layer 1
    agg_kernel<F1><<<N2_NODES / 8, 256>>>(h1, src[1], agg, N2_NODES);
    gemm_dual_kernel<0><<<N2_NODES / 128, 256, SMEM_BYTES>>>(
        agg, h1, Wl[1], Wr[1], h2);

    // Layer 2 (log_softmax fused)
    agg_kernel<F2><<<N3_NODES / 8, 256>>>(h2, src[2], agg, N3_NODES);
    gemm_dual_kernel<1><<<N3_NODES / 128, 256, SMEM_BYTES>>>(
        agg, h2, Wl[2], Wr[2], out);
}

// round 5
// speedup vs baseline: 1.3475x; 1.0692x over previous
#include <cuda_runtime.h>
#include <cuda_bf16.h>
#include <cstdint>

// ---------------------------------------------------------------------------
// Problem constants (fixed by setup_inputs)
// ---------------------------------------------------------------------------
#define D          128
#define N0_NODES   1081344
#define N1_NODES   67584
#define N2_NODES   6144
#define N3_NODES   1024
#define F0         15
#define F1         10
#define F2         5

// Scratch (no cudaMalloc allowed)
__device__ float g_agg[N1_NODES * D];
__device__ float g_h1 [N1_NODES * D];
__device__ float g_h2 [N2_NODES * D];

// ---------------------------------------------------------------------------
// Aggregation: warp per target, mean of F gathered 512B rows. (control)
// ---------------------------------------------------------------------------
template <int F>
__global__ void __launch_bounds__(256) agg_kernel(
    const float* __restrict__ x, const int* __restrict__ src,
    float* __restrict__ agg, int nt)
{
    int warp = blockIdx.x * 8 + (threadIdx.x >> 5);
    int lane = threadIdx.x & 31;
    if (warp >= nt) return;

    const float4* xv = reinterpret_cast<const float4*>(x);
    const int* sp = src + warp * F;

    int rows[F];
#pragma unroll
    for (int j = 0; j < F; j++) rows[j] = __ldg(sp + j);

    float4 s = make_float4(0.f, 0.f, 0.f, 0.f);
#pragma unroll
    for (int j = 0; j < F; j++) {
        float4 v = __ldg(&xv[(long)rows[j] * 32 + lane]);
        s.x += v.x; s.y += v.y; s.z += v.z; s.w += v.w;
    }
    const float invf = 1.0f / (float)F;
    s.x *= invf; s.y *= invf; s.z *= invf; s.w *= invf;
    reinterpret_cast<float4*>(agg)[(long)warp * 32 + lane] = s;
}

// ---------------------------------------------------------------------------
// helpers
// ---------------------------------------------------------------------------
__device__ __forceinline__ void mma_tf32(float c[4], const uint32_t a[4],
                                         const uint32_t b[2]) {
    asm volatile(
        "mma.sync.aligned.m16n8k8.row.col.f32.tf32.tf32.f32 "
        "{%0,%1,%2,%3}, {%4,%5,%6,%7}, {%8,%9}, {%0,%1,%2,%3};"
        : "+f"(c[0]), "+f"(c[1]), "+f"(c[2]), "+f"(c[3])
        : "r"(a[0]), "r"(a[1]), "r"(a[2]), "r"(a[3]), "r"(b[0]), "r"(b[1]));
}
__device__ __forceinline__ void ldsm_x4(uint32_t a[4], uint32_t addr) {
    asm volatile("ldmatrix.sync.aligned.m8n8.x4.shared.b16 {%0,%1,%2,%3}, [%4];"
        : "=r"(a[0]), "=r"(a[1]), "=r"(a[2]), "=r"(a[3]) : "r"(addr));
}
__device__ __forceinline__ void ldsm_x2(uint32_t b[2], uint32_t addr) {
    asm volatile("ldmatrix.sync.aligned.m8n8.x2.shared.b16 {%0,%1}, [%2];"
        : "=r"(b[0]), "=r"(b[1]) : "r"(addr));
}
__device__ __forceinline__ void cp_async16(uint32_t saddr, const void* gptr) {
    asm volatile("cp.async.cg.shared.global [%0], [%1], 16;" ::
                 "r"(saddr), "l"(gptr));
}

// ---------------------------------------------------------------------------
// Persistent dual GEMM: out[M,128] = Agg[M,128]@Wl^T + X[M,128]@Wr^T
// A = [Agg | X] (256 k), B = [Wl ; Wr] (n-major, raw fp32; tf32 truncation
// happens inside the HMMA). B staged ONCE per block; per-block tile loop with
// a rolling 2-buffer cp.async chunk pipeline spanning tile boundaries.
// MODE 0: ReLU epilogue. MODE 1: log_softmax epilogue (requires 1 tile/block —
// launch with grid == numTiles).
// ---------------------------------------------------------------------------
#define AS_STRIDE 68                 // words per A row (64 k + pad)
#define BS_STRIDE 260                // words per B row (256 k + pad)
#define AS_WORDS  (128 * AS_STRIDE)
#define BS_WORDS  (128 * BS_STRIDE)
#define SMEM_BYTES ((BS_WORDS + 2 * AS_WORDS) * 4)

template <int MODE>
__global__ void __launch_bounds__(256, 1) gemm_persist(
    const float* __restrict__ Aagg, const float* __restrict__ X,
    const float* __restrict__ Wl,   const float* __restrict__ Wr,
    float* __restrict__ out, int numTiles)
{
    extern __shared__ uint32_t smem[];
    uint32_t* Bs = smem;                // [128 n][260]
    uint32_t* As = smem + BS_WORDS;     // [2][128 m][68]

    const int tid  = threadIdx.x;
    const int lane = tid & 31;
    const int wid  = tid >> 5;
    const int wm   = wid & 3;           // 4 warp rows x 32 m
    const int wn   = wid >> 2;          // 2 warp cols x 64 n

    const uint32_t as_base = (uint32_t)__cvta_generic_to_shared(As);
    const uint32_t bs_base = (uint32_t)__cvta_generic_to_shared(Bs);

    // ---- stage B once (raw fp32), single commit group, full MLP ----
#pragma unroll
    for (int i = 0; i < 32; i++) {
        int idx = i * 256 + tid;
        int n   = idx >> 6;
        int seg = idx & 63;             // 16B segment: k = seg*4
        const float* g = (seg < 32) ? (Wl + n * 128 + seg * 4)
                                    : (Wr + n * 128 + (seg - 32) * 4);
        cp_async16(bs_base + (uint32_t)(n * BS_STRIDE * 4 + seg * 16), g);
    }
    asm volatile("cp.async.commit_group;" ::);

    // tiles for this block: t = blockIdx.x + j*gridDim.x
    const int myTiles = (numTiles - blockIdx.x + gridDim.x - 1) / gridDim.x;
    const int totalQ  = myTiles * 4;    // 4 chunks per tile

    // chunk q: tile t = blockIdx.x + (q>>2)*gridDim.x, c = q&3, buf = q&1
    auto issue = [&](int q) {
        const int c = q & 3;
        const long blockM = (long)(blockIdx.x + (q >> 2) * gridDim.x) * 128;
        const float* src = (c < 2) ? Aagg : X;
        const int koff = (c & 1) * 64;
        const uint32_t sbase = as_base + (uint32_t)(q & 1) * (AS_WORDS * 4);
#pragma unroll
        for (int i = 0; i < 8; i++) {
            int idx = i * 256 + tid;
            int seg = idx & 15;
            int row = idx >> 4;
            cp_async16(sbase + (uint32_t)(row * (AS_STRIDE * 4) + seg * 16),
                       src + (blockM + row) * 128 + koff + seg * 4);
        }
        asm volatile("cp.async.commit_group;" ::);
    };

    issue(0);
    if (totalQ > 1) issue(1);

    float acc[2][8][4];
#pragma unroll
    for (int mi = 0; mi < 2; mi++)
#pragma unroll
        for (int ni = 0; ni < 8; ni++)
#pragma unroll
            for (int q = 0; q < 4; q++) acc[mi][ni][q] = 0.f;

    const uint32_t a_lane = (uint32_t)((wm * 32 + (lane & 15)) * (AS_STRIDE * 4)
                                       + (lane >> 4) * 16);
    const uint32_t b_lane = (uint32_t)((wn * 64 + (lane & 7)) * (BS_STRIDE * 4)
                                       + ((lane >> 3) & 1) * 16);

#pragma unroll 1
    for (int q = 0; q < totalQ; q++) {
        if (q == totalQ - 1) asm volatile("cp.async.wait_group 0;" ::);
        else                 asm volatile("cp.async.wait_group 1;" ::);
        __syncthreads();

        const uint32_t abuf = as_base + (uint32_t)(q & 1) * (AS_WORDS * 4);
        const int chunkK = (q & 3) * 64;
#pragma unroll
        for (int kb = 0; kb < 64; kb += 8) {
            const int gk = chunkK + kb;
            uint32_t bf[8][2];
#pragma unroll
            for (int ni = 0; ni < 8; ni++)
                ldsm_x2(bf[ni], bs_base + b_lane
                                + (uint32_t)(ni * 8 * BS_STRIDE * 4) + gk * 4);
            uint32_t af[2][4];
#pragma unroll
            for (int mi = 0; mi < 2; mi++)
                ldsm_x4(af[mi], abuf + a_lane
                                + (uint32_t)(mi * 16 * AS_STRIDE * 4) + kb * 4);
#pragma unroll
            for (int mi = 0; mi < 2; mi++)
#pragma unroll
                for (int ni = 0; ni < 8; ni++)
                    mma_tf32(acc[mi][ni], af[mi], bf[ni]);
        }
        __syncthreads();
        if (q + 2 < totalQ) issue(q + 2);

        if ((q & 3) == 3) {
            const long blockM = (long)(blockIdx.x + (q >> 2) * gridDim.x) * 128;
            if (MODE == 0) {
                // ---- ReLU epilogue ----
#pragma unroll
                for (int mi = 0; mi < 2; mi++) {
#pragma unroll
                    for (int ni = 0; ni < 8; ni++) {
                        long row = blockM + wm * 32 + mi * 16 + (lane >> 2);
                        int  col = wn * 64 + ni * 8 + (lane & 3) * 2;
                        float2 lo = make_float2(fmaxf(acc[mi][ni][0], 0.f),
                                                fmaxf(acc[mi][ni][1], 0.f));
                        float2 hi = make_float2(fmaxf(acc[mi][ni][2], 0.f),
                                                fmaxf(acc[mi][ni][3], 0.f));
                        *(float2*)(out + row * 128 + col)       = lo;
                        *(float2*)(out + (row + 8) * 128 + col) = hi;
                    }
                }
            } else {
                // ---- log_softmax epilogue (1 tile/block; reuses A smem) ----
                float* Ls = reinterpret_cast<float*>(As);   // [128][132]
#pragma unroll
                for (int mi = 0; mi < 2; mi++) {
#pragma unroll
                    for (int ni = 0; ni < 8; ni++) {
                        int row = wm * 32 + mi * 16 + (lane >> 2);
                        int col = wn * 64 + ni * 8 + (lane & 3) * 2;
                        *(float2*)(Ls + row * 132 + col) =
                            make_float2(acc[mi][ni][0], acc[mi][ni][1]);
                        *(float2*)(Ls + (row + 8) * 132 + col) =
                            make_float2(acc[mi][ni][2], acc[mi][ni][3]);
                    }
                }
                __syncthreads();
#pragma unroll 1
                for (int i = 0; i < 16; i++) {
                    int r = wid * 16 + i;
                    float4 v = *reinterpret_cast<float4*>(Ls + r * 132 + lane * 4);
                    float m = fmaxf(fmaxf(v.x, v.y), fmaxf(v.z, v.w));
#pragma unroll
                    for (int o = 16; o > 0; o >>= 1)
                        m = fmaxf(m, __shfl_xor_sync(0xFFFFFFFF, m, o));
                    float s = expf(v.x - m) + expf(v.y - m)
                            + expf(v.z - m) + expf(v.w - m);
#pragma unroll
                    for (int o = 16; o > 0; o >>= 1)
                        s += __shfl_xor_sync(0xFFFFFFFF, s, o);
                    float lse = m + logf(s);
                    float4 rr = make_float4(v.x - lse, v.y - lse,
                                            v.z - lse, v.w - lse);
                    *reinterpret_cast<float4*>(
                        out + (blockM + r) * 128 + lane * 4) = rr;
                }
            }
            // reset accumulators for next tile
#pragma unroll
            for (int mi = 0; mi < 2; mi++)
#pragma unroll
                for (int ni = 0; ni < 8; ni++)
#pragma unroll
                    for (int z = 0; z < 4; z++) acc[mi][ni][z] = 0.f;
        }
    }
}

// ---------------------------------------------------------------------------
// Launch
// ---------------------------------------------------------------------------
extern "C" void kernel_launch(void* const* d_in, const int* in_sizes, int n_in,
                              void* d_out, int out_size)
{
    const long X_SZ = (long)N0_NODES * D;
    const int  W_SZ = D * D;

    const float* x = nullptr;
    const float* Wl[3] = {nullptr, nullptr, nullptr};
    const float* Wr[3] = {nullptr, nullptr, nullptr};
    const int*   src[3] = {nullptr, nullptr, nullptr};

    if ((long)in_sizes[0] == X_SZ && in_sizes[1] == W_SZ) {
        x = (const float*)d_in[0];
        for (int i = 0; i < 3; i++) {
            Wl[i]  = (const float*)d_in[1 + 2 * i];
            Wr[i]  = (const float*)d_in[2 + 2 * i];
            src[i] = (const int*)  d_in[7 + 2 * i];
        }
    } else if ((long)in_sizes[0] == X_SZ) {
        x = (const float*)d_in[0];
        for (int i = 0; i < 3; i++) {
            src[i] = (const int*)  d_in[1 + 4 * i];
            Wl[i]  = (const float*)d_in[3 + 4 * i];
            Wr[i]  = (const float*)d_in[4 + 4 * i];
        }
    } else {
        for (int i = 0; i < 3; i++) {
            Wl[i]  = (const float*)d_in[i];
            Wr[i]  = (const float*)d_in[3 + i];
            src[i] = (const int*)  d_in[9 + i];
        }
        x = (const float*)d_in[12];
    }

    float *agg, *h1, *h2;
    cudaGetSymbolAddress((void**)&agg, g_agg);
    cudaGetSymbolAddress((void**)&h1,  g_h1);
    cudaGetSymbolAddress((void**)&h2,  g_h2);

    cudaFuncSetAttribute(gemm_persist<0>,
        cudaFuncAttributeMaxDynamicSharedMemorySize, SMEM_BYTES);
    cudaFuncSetAttribute(gemm_persist<1>,
        cudaFuncAttributeMaxDynamicSharedMemorySize, SMEM_BYTES);

    float* out = (float*)d_out;

    const int T0 = N1_NODES / 128;   // 528
    const int T1 = N2_NODES / 128;   // 48
    const int T2 = N3_NODES / 128;   // 8

    // Layer 0
    agg_kernel<F0><<<N1_NODES / 8, 256>>>(x, src[0], agg, N1_NODES);
    gemm_persist<0><<<(T0 < 148 ? T0 : 148), 256, SMEM_BYTES>>>(
        agg, x, Wl[0], Wr[0], h1, T0);

    // Layer 1
    agg_kernel<F1><<<N2_NODES / 8, 256>>>(h1, src[1], agg, N2_NODES);
    gemm_persist<0><<<T1, 256, SMEM_BYTES>>>(
        agg, h1, Wl[1], Wr[1], h2, T1);

    // Layer 2 (log_softmax fused; grid MUST equal numTiles for MODE 1)
    agg_kernel<F2><<<N3_NODES / 8, 256>>>(h2, src[2], agg, N3_NODES);
    gemm_persist<1><<<T2, 256, SMEM_BYTES>>>(
        agg, h2, Wl[2], Wr[2], out, T2);
}